// round 13
// baseline (speedup 1.0000x reference)
#include <cuda_runtime.h>
#include <math.h>
#include <stdint.h>

#define Bm   64
#define Tm   512
#define Hm   512
#define Cm   64
#define NBLK 128
#define NTHR 512
#define KH   256            // K half-tile
#define WST  260            // padded weight row stride (floats) - bank-conflict-free
// smem (floats): hH[2][KH*Bm] | wH[2][32*WST] | sg[4][32*64]
#define OFF_H(s)  ((s) * KH * Bm)
#define OFF_W(s)  (2 * KH * Bm + (s) * 32 * WST)
#define OFF_SG    (2 * KH * Bm + 2 * 32 * WST)
#define SM_WORDS  (OFF_SG + 4 * 32 * 64)
#define SM_BYTES  (SM_WORDS * 4)
#define SQ   260
#define FC_SM_BYTES (128 * SQ * 4)

// Persistent scratch.  Recurrent state is K-MAJOR: s[k*64 + b].
__device__ float g_h1[2][2][Hm * Bm];   // [dir][parity]
__device__ float g_c1[2][2][Hm * Bm];
__device__ float g_h2[2][2][Hm * Bm];
__device__ float g_c2[2][Hm * Bm];      // block-local
__device__ float g_hist[2][Tm][Bm * Hm];  // b-major (fc consumes)
__device__ unsigned g_cnt2[2] = {0, 0};
__device__ unsigned g_gen = 0;          // monotonic event counter

__device__ __forceinline__ void fma4(float s, const float4 v, float4& a) {
    a.x = fmaf(s, v.x, a.x); a.y = fmaf(s, v.y, a.y);
    a.z = fmaf(s, v.z, a.z); a.w = fmaf(s, v.w, a.w);
}
__device__ __forceinline__ float sigf(float x) { return 1.0f / (1.0f + expf(-x)); }
__device__ __forceinline__ int jrow(int r, int hcb) {
    return ((r >> 3) << 9) + hcb + (r & 7);
}

// ---- split grid barrier ----
__device__ __forceinline__ void ev_arrive(int par) {
    __threadfence();
    __syncthreads();
    if (threadIdx.x == 0) {
        if (atomicAdd(&g_cnt2[par], 1u) == NBLK - 1) {
            g_cnt2[par] = 0;
            __threadfence();
            atomicAdd(&g_gen, 1u);
        }
    }
}
__device__ __forceinline__ void ev_wait(unsigned base, unsigned n) {
    if (threadIdx.x == 0) {
        while ((int)(*(volatile unsigned*)&g_gen - base) < (int)n) {}
        __threadfence();
    }
    __syncthreads();
}

// ---- cp.async ----
__device__ __forceinline__ unsigned smaddr(const void* p) {
    unsigned a;
    asm("{.reg .u64 t; cvta.to.shared.u64 t, %1; cvt.u32.u64 %0, t;}"
        : "=r"(a) : "l"(p));
    return a;
}
__device__ __forceinline__ void cpa16(unsigned d, const float* s) {
    asm volatile("cp.async.cg.shared.global [%0], [%1], 16;" :: "r"(d), "l"(s));
}
#define CP_COMMIT() asm volatile("cp.async.commit_group;")
#define CP_WAIT0()  asm volatile("cp.async.wait_group 0;" ::: "memory")

// Prefetch one half-pass operand set (pure cp.async, no transpose).
__device__ __forceinline__ void prefetch_half(float* sm, int slot,
                                              const float* __restrict__ hsrc,
                                              const float* __restrict__ wsrc,
                                              int k0, int hcb, int tid) {
    unsigned hd = smaddr(sm + OFF_H(slot));
    const float* hp = hsrc + k0 * Bm;
#pragma unroll
    for (int i = 0; i < 8; ++i) {
        int c = tid + NTHR * i;          // 0..4095 16B chunks
        cpa16(hd + c * 16, hp + c * 4);
    }
    unsigned wd = smaddr(sm + OFF_W(slot));
#pragma unroll
    for (int i = 0; i < 4; ++i) {
        int c = tid + NTHR * i;          // 0..2047 chunks
        int r = c >> 6, cc = c & 63;
        cpa16(wd + (r * WST + cc * 4) * 4,
              wsrc + (size_t)jrow(r, hcb) * Hm + k0 + cc * 4);
    }
    CP_COMMIT();
}

// Half-pass GEMM, 4-way K-split: group ks handles k in [ks*64, ks*64+64) of the half.
// Thread tile: 4 gate rows (rows rg, rg+8, rg+16, rg+24) x 4 batches.
__device__ __forceinline__ void gemm_half(const float* sm, int slot,
                                          int rg, int b0, int ks,
                                          float4 acc[4]) {
    const float* wbase = sm + OFF_W(slot);
    const float4* w0p = (const float4*)(wbase + (0 * 8 + rg) * WST) + ks * 16;
    const float4* w1p = (const float4*)(wbase + (1 * 8 + rg) * WST) + ks * 16;
    const float4* w2p = (const float4*)(wbase + (2 * 8 + rg) * WST) + ks * 16;
    const float4* w3p = (const float4*)(wbase + (3 * 8 + rg) * WST) + ks * 16;
    const float* hb = sm + OFF_H(slot) + (ks * 64) * Bm + b0;
#pragma unroll 4
    for (int kq = 0; kq < 16; ++kq) {
        float4 w0 = w0p[kq];
        float4 w1 = w1p[kq];
        float4 w2 = w2p[kq];
        float4 w3 = w3p[kq];
        const float* hq = hb + kq * 4 * Bm;
        float4 h0 = *(const float4*)(hq);
        float4 h1 = *(const float4*)(hq + Bm);
        float4 h2 = *(const float4*)(hq + 2 * Bm);
        float4 h3 = *(const float4*)(hq + 3 * Bm);
        fma4(w0.x, h0, acc[0]); fma4(w0.y, h1, acc[0]); fma4(w0.z, h2, acc[0]); fma4(w0.w, h3, acc[0]);
        fma4(w1.x, h0, acc[1]); fma4(w1.y, h1, acc[1]); fma4(w1.z, h2, acc[1]); fma4(w1.w, h3, acc[1]);
        fma4(w2.x, h0, acc[2]); fma4(w2.y, h1, acc[2]); fma4(w2.z, h2, acc[2]); fma4(w2.w, h3, acc[2]);
        fma4(w3.x, h0, acc[3]); fma4(w3.y, h1, acc[3]); fma4(w3.z, h2, acc[3]); fma4(w3.w, h3, acc[3]);
    }
}

__global__ void noop_kernel() {}

extern "C" __global__ void __launch_bounds__(NTHR, 1)
lstm_persist(const float* __restrict__ x,
             const float* wih1, const float* whh1, const float* bih1, const float* bhh1,
             const float* wih2, const float* whh2, const float* bih2, const float* bhh2,
             const float* wih3, const float* whh3, const float* bih3, const float* bhh3,
             const float* wih4, const float* whh4, const float* bih4, const float* bhh4) {
    extern __shared__ __align__(16) float sm[];
    float* sg = sm + OFF_SG;             // [4][32][64] partial gates

    const int tid = threadIdx.x;
    const int dir = blockIdx.x & 1;
    const int gb  = blockIdx.x >> 1;
    const int hcb = gb << 3;

    const unsigned gbase = *(volatile unsigned*)&g_gen;

    const float* WIH1 = dir ? wih3 : wih1;
    const float* WHH1 = dir ? whh3 : whh1;
    const float* BIH1 = dir ? bih3 : bih1;
    const float* BHH1 = dir ? bhh3 : bhh1;
    const float* WIH2 = dir ? wih4 : wih2;
    const float* WHH2 = dir ? whh4 : whh2;
    const float* BIH2 = dir ? bih4 : bih2;
    const float* BHH2 = dir ? bhh4 : bhh2;

    // zero persistent state (event 1)
    {
        const int gt = blockIdx.x * NTHR + tid;
        const int stride = NBLK * NTHR;
        float* h1f = (float*)g_h1;
        float* c1f = (float*)g_c1;
        float* h2f = (float*)g_h2;
        float* c2f = (float*)g_c2;
        for (int i = gt; i < 2 * 2 * Hm * Bm; i += stride) {
            __stcg(&h1f[i], 0.0f); __stcg(&h2f[i], 0.0f); __stcg(&c1f[i], 0.0f);
        }
        for (int i = gt; i < 2 * Hm * Bm; i += stride) __stcg(&c2f[i], 0.0f);
    }
    ev_arrive(1);
    ev_wait(gbase, 1);

    // thread org: ks = K-quarter group (0..3); warp = 2 hcols x 16 batch-quads
    const int ks   = tid >> 7;
    const int lane = tid & 31;
    const int wg   = (tid >> 5) & 3;
    const int bq   = lane & 15;
    const int rgl  = lane >> 4;
    const int rg   = wg * 2 + rgl;       // hidden col 0..7
    const int b0   = bq << 2;

    // global gate rows for this thread's hidden column
    const int jg0 = 0 * 512 + hcb + rg;
    const int jg1 = 1 * 512 + hcb + rg;
    const int jg2 = 2 * 512 + hcb + rg;
    const int jg3 = 3 * 512 + hcb + rg;

    float4 bias1, bias2, xw;
    if (ks == 0) {
        bias1 = make_float4(__ldg(BIH1 + jg0) + __ldg(BHH1 + jg0),
                            __ldg(BIH1 + jg1) + __ldg(BHH1 + jg1),
                            __ldg(BIH1 + jg2) + __ldg(BHH1 + jg2),
                            __ldg(BIH1 + jg3) + __ldg(BHH1 + jg3));
        bias2 = make_float4(__ldg(BIH2 + jg0) + __ldg(BHH2 + jg0),
                            __ldg(BIH2 + jg1) + __ldg(BHH2 + jg1),
                            __ldg(BIH2 + jg2) + __ldg(BHH2 + jg2),
                            __ldg(BIH2 + jg3) + __ldg(BHH2 + jg3));
        xw = make_float4(__ldg(WIH1 + jg0), __ldg(WIH1 + jg1),
                         __ldg(WIH1 + jg2), __ldg(WIH1 + jg3));
    } else {
        bias1 = bias2 = xw = make_float4(0.f, 0.f, 0.f, 0.f);
    }

    // gate/activation mapping: one (hcol, batch) pair per thread (512 pairs)
    const int hc = tid >> 6, ab = tid & 63;
    const int kx = (hcb + hc) * Bm + ab;     // k-major state index

    // prime pipeline: item1 of t=0 = (h1 zeros, WHH1, half0) -> slot0
    prefetch_half(sm, 0, g_h1[dir][1], WHH1, 0, hcb, tid);

#pragma unroll 1
    for (int t = 0; t < Tm; ++t) {
        const int wb = t & 1, rb = wb ^ 1;
        const int te = dir ? (Tm - 1 - t) : t;
        const float* h1r = g_h1[dir][rb];
        const float* h2r = g_h2[dir][rb];
        const float* c1w = g_c1[dir][wb];

        // ---- item1: pass1 half0 ----
        CP_WAIT0(); __syncthreads();
        prefetch_half(sm, 1, h1r, WHH1, KH, hcb, tid);      // item2
        float4 acc[4];
        acc[0] = make_float4(bias1.x, bias1.x, bias1.x, bias1.x);
        acc[1] = make_float4(bias1.y, bias1.y, bias1.y, bias1.y);
        acc[2] = make_float4(bias1.z, bias1.z, bias1.z, bias1.z);
        acc[3] = make_float4(bias1.w, bias1.w, bias1.w, bias1.w);
        if (ks == 0) {
            float4 xv = make_float4(__ldg(x + (b0 + 0) * Tm + te),
                                    __ldg(x + (b0 + 1) * Tm + te),
                                    __ldg(x + (b0 + 2) * Tm + te),
                                    __ldg(x + (b0 + 3) * Tm + te));
            fma4(xw.x, xv, acc[0]);
            fma4(xw.y, xv, acc[1]);
            fma4(xw.z, xv, acc[2]);
            fma4(xw.w, xv, acc[3]);
        }
        gemm_half(sm, 0, rg, b0, ks, acc);

        // ---- item2: pass1 half1 ----
        CP_WAIT0(); __syncthreads();
        ev_wait(gbase, 2u * t + 1u);                        // evB(t-1)
        prefetch_half(sm, 0, h2r, WHH2, 0, hcb, tid);       // item3
        gemm_half(sm, 1, rg, b0, ks, acc);

        // ---- gates 1: reduce 4 partials, write c1(t), h1(t) ----
#pragma unroll
        for (int g = 0; g < 4; ++g)
            *(float4*)(sg + ks * 2048 + (g * 8 + rg) * 64 + b0) = acc[g];
        __syncthreads();
        {
            float gi = sg[(0 * 8 + hc) * 64 + ab] + sg[2048 + (0 * 8 + hc) * 64 + ab]
                     + sg[4096 + (0 * 8 + hc) * 64 + ab] + sg[6144 + (0 * 8 + hc) * 64 + ab];
            float gf = sg[(1 * 8 + hc) * 64 + ab] + sg[2048 + (1 * 8 + hc) * 64 + ab]
                     + sg[4096 + (1 * 8 + hc) * 64 + ab] + sg[6144 + (1 * 8 + hc) * 64 + ab];
            float gg = sg[(2 * 8 + hc) * 64 + ab] + sg[2048 + (2 * 8 + hc) * 64 + ab]
                     + sg[4096 + (2 * 8 + hc) * 64 + ab] + sg[6144 + (2 * 8 + hc) * 64 + ab];
            float go = sg[(3 * 8 + hc) * 64 + ab] + sg[2048 + (3 * 8 + hc) * 64 + ab]
                     + sg[4096 + (3 * 8 + hc) * 64 + ab] + sg[6144 + (3 * 8 + hc) * 64 + ab];
            float cold = __ldcg(&g_c1[dir][rb][kx]);
            float cn = sigf(gf) * cold + sigf(gi) * tanhf(gg);
            __stcg(&g_c1[dir][wb][kx], cn);
            __stcg(&g_h1[dir][wb][kx], sigf(go) * tanhf(cn));
        }
        ev_arrive(0);                                       // evA(t)

        // ---- item3: pass2 half0 (WHH2 @ h2(t-1)) ----
        CP_WAIT0(); __syncthreads();
        prefetch_half(sm, 1, h2r, WHH2, KH, hcb, tid);      // item4
        acc[0] = make_float4(bias2.x, bias2.x, bias2.x, bias2.x);
        acc[1] = make_float4(bias2.y, bias2.y, bias2.y, bias2.y);
        acc[2] = make_float4(bias2.z, bias2.z, bias2.z, bias2.z);
        acc[3] = make_float4(bias2.w, bias2.w, bias2.w, bias2.w);
        gemm_half(sm, 0, rg, b0, ks, acc);

        // ---- item4: pass2 half1 ----
        CP_WAIT0(); __syncthreads();
        ev_wait(gbase, 2u * t + 2u);                        // evA(t)
        prefetch_half(sm, 0, c1w, WIH2, 0, hcb, tid);       // item5
        gemm_half(sm, 1, rg, b0, ks, acc);

        // ---- item5: pass3 half0 (WIH2 @ c1(t)) ----
        CP_WAIT0(); __syncthreads();
        prefetch_half(sm, 1, c1w, WIH2, KH, hcb, tid);      // item6
        gemm_half(sm, 0, rg, b0, ks, acc);

        // ---- item6: pass3 half1; prefetch next step's item1 ----
        CP_WAIT0(); __syncthreads();
        prefetch_half(sm, 0, g_h1[dir][wb], WHH1, 0, hcb, tid);
        gemm_half(sm, 1, rg, b0, ks, acc);

        // ---- gates 2: reduce 4 partials, write c2, h2(t), hist ----
#pragma unroll
        for (int g = 0; g < 4; ++g)
            *(float4*)(sg + ks * 2048 + (g * 8 + rg) * 64 + b0) = acc[g];
        __syncthreads();
        {
            float gi = sg[(0 * 8 + hc) * 64 + ab] + sg[2048 + (0 * 8 + hc) * 64 + ab]
                     + sg[4096 + (0 * 8 + hc) * 64 + ab] + sg[6144 + (0 * 8 + hc) * 64 + ab];
            float gf = sg[(1 * 8 + hc) * 64 + ab] + sg[2048 + (1 * 8 + hc) * 64 + ab]
                     + sg[4096 + (1 * 8 + hc) * 64 + ab] + sg[6144 + (1 * 8 + hc) * 64 + ab];
            float gg = sg[(2 * 8 + hc) * 64 + ab] + sg[2048 + (2 * 8 + hc) * 64 + ab]
                     + sg[4096 + (2 * 8 + hc) * 64 + ab] + sg[6144 + (2 * 8 + hc) * 64 + ab];
            float go = sg[(3 * 8 + hc) * 64 + ab] + sg[2048 + (3 * 8 + hc) * 64 + ab]
                     + sg[4096 + (3 * 8 + hc) * 64 + ab] + sg[6144 + (3 * 8 + hc) * 64 + ab];
            float cold = __ldcg(&g_c2[dir][kx]);
            float cn = sigf(gf) * cold + sigf(gi) * tanhf(gg);
            __stcg(&g_c2[dir][kx], cn);
            __stcg(&g_h2[dir][wb][kx], sigf(go) * tanhf(cn));
            g_hist[dir][t][ab * Hm + hcb + hc] = cn;
        }
        ev_arrive(1);                                       // evB(t)
    }
    ev_wait(gbase, 2u * Tm + 1u);   // drain
}

// ---- final FC (unchanged) ----
__device__ __forceinline__ void stage_T(const float* __restrict__ src,
                                        float* __restrict__ sT, int tid) {
#pragma unroll
    for (int it = 0; it < 32; ++it) {
        int id   = tid + 256 * it;
        int lane = id & 31;
        int grp  = id >> 5;
        int kl   = lane & 7;
        int bg   = lane >> 3;
        int kq   = ((grp & 15) << 3) | kl;
        int b    = ((grp >> 4) << 2) | bg;
        float4 v = __ldcg((const float4*)(src + b * Hm + (kq << 2)));
        float* p = sT + kq * SQ + b;
        p[0] = v.x; p[64] = v.y; p[128] = v.z; p[192] = v.w;
    }
}

extern "C" __global__ void __launch_bounds__(256)
fc_kernel(const float* __restrict__ fcw, const float* __restrict__ fcb,
          const float* __restrict__ bfcw, const float* __restrict__ bfcb,
          float* __restrict__ out) {
    extern __shared__ __align__(16) float smf[];
    float* sT = smf;
    const int tid = threadIdx.x;
    const int d = blockIdx.x >> 9;
    const int t = blockIdx.x & 511;
    const float* W = d ? bfcw : fcw;
    const float* bias = d ? bfcb : fcb;

    stage_T(W, sT, tid);
    __syncthreads();

    const float* hb = g_hist[d][t];
    const size_t obase = (size_t)d * Bm * Tm * Cm + (size_t)t * Cm;

#pragma unroll
    for (int tt = 0; tt < 4; ++tt) {
        int tile = tid + 256 * tt;
        int b = tile >> 4;
        int c0 = (tile & 15) << 2;
        float4 acc = *(const float4*)(bias + c0);
        const float4* hq = (const float4*)(hb + b * Hm);
        const float* wq0 = sT + c0;
#pragma unroll 4
        for (int kq = 0; kq < 128; ++kq) {
            float4 h4 = __ldg(hq + kq);
            const float* wq = wq0 + kq * SQ;
            fma4(h4.x, *(const float4*)(wq), acc);
            fma4(h4.y, *(const float4*)(wq + 64), acc);
            fma4(h4.z, *(const float4*)(wq + 128), acc);
            fma4(h4.w, *(const float4*)(wq + 192), acc);
        }
        *(float4*)(out + obase + (size_t)b * Tm * Cm + c0) = acc;
    }
}

extern "C" void kernel_launch(void* const* d_in, const int* in_sizes, int n_in,
                              void* d_out, int out_size) {
    const float* x    = (const float*)d_in[0];
    const float* wih1 = (const float*)d_in[1];
    const float* whh1 = (const float*)d_in[2];
    const float* bih1 = (const float*)d_in[3];
    const float* bhh1 = (const float*)d_in[4];
    const float* wih2 = (const float*)d_in[5];
    const float* whh2 = (const float*)d_in[6];
    const float* bih2 = (const float*)d_in[7];
    const float* bhh2 = (const float*)d_in[8];
    const float* wih3 = (const float*)d_in[9];
    const float* whh3 = (const float*)d_in[10];
    const float* bih3 = (const float*)d_in[11];
    const float* bhh3 = (const float*)d_in[12];
    const float* wih4 = (const float*)d_in[13];
    const float* whh4 = (const float*)d_in[14];
    const float* bih4 = (const float*)d_in[15];
    const float* bhh4 = (const float*)d_in[16];
    const float* fcw  = (const float*)d_in[17];
    const float* fcb  = (const float*)d_in[18];
    const float* bfcw = (const float*)d_in[19];
    const float* bfcb = (const float*)d_in[20];

    static int attr_done = 0;
    if (!attr_done) {
        cudaFuncSetAttribute(lstm_persist, cudaFuncAttributeMaxDynamicSharedMemorySize, SM_BYTES);
        cudaFuncSetAttribute(fc_kernel, cudaFuncAttributeMaxDynamicSharedMemorySize, FC_SM_BYTES);
        attr_done = 1;
    }

    // 3 noops: with 2 hidden harness launches, ncu -s 5 -c 1 lands on lstm_persist
    for (int i = 0; i < 3; ++i) noop_kernel<<<1, 32>>>();

    lstm_persist<<<NBLK, NTHR, SM_BYTES>>>(x,
        wih1, whh1, bih1, bhh1, wih2, whh2, bih2, bhh2,
        wih3, whh3, bih3, bhh3, wih4, whh4, bih4, bhh4);

    fc_kernel<<<2 * Tm, 256, FC_SM_BYTES>>>(fcw, fcb, bfcw, bfcb, (float*)d_out);
}

// round 14
// speedup vs baseline: 1.2150x; 1.2150x over previous
#include <cuda_runtime.h>
#include <cuda_bf16.h>
#include <math.h>
#include <stdint.h>

#define Bm 64
#define Tm 512
#define Hm 512
#define Cm 64
#define NBLK 128
#define NTHR 256
#define KC 128                 // K chunk
#define KHP 136                // padded smem row stride (bf16 units), ==8 mod 64
// slot regions (bf16 units within a slot)
#define S_WHI 0
#define S_WLO (32*KHP)
#define S_HHI (64*KHP)
#define S_HLO (128*KHP)
#define SLOT_BF (192*KHP)      // 26112 bf16 per slot
// float regions (float index into smem) after 2 slots (2*26112 bf16 = 26112 floats)
#define F_SG   26112
#define F_CS   (F_SG + 4*2048) // c1f[512], c2f[512]
#define F_B1   (F_CS + 1024)
#define F_B2   (F_B1 + 32)
#define F_XW   (F_B2 + 32)
#define SM_FLOATS (F_XW + 32)
#define SM_BYTES (SM_FLOATS*4)
#define SQ 260
#define FC_SMB (128*SQ*4)

// weight planes, block-ordered: [dir*3+pass][gb][r*512+k]
__device__ __nv_bfloat16 gWh[6][64][32*512];
__device__ __nv_bfloat16 gWl[6][64][32*512];
// state planes, b-major [b*512+k]
__device__ __nv_bfloat16 gH1h[2][2][Bm*Hm], gH1l[2][2][Bm*Hm]; // [dir][parity]
__device__ __nv_bfloat16 gH2h[2][2][Bm*Hm], gH2l[2][2][Bm*Hm];
__device__ __nv_bfloat16 gC1h[2][Bm*Hm],    gC1l[2][Bm*Hm];    // [dir]
__device__ float g_hist[2][Tm][Bm*Hm];
__device__ unsigned g_cnt2[2] = {0, 0};
__device__ unsigned g_gen = 0;

__device__ __forceinline__ float sigf(float v){ return 1.f/(1.f+expf(-v)); }
__device__ __forceinline__ void fma4(float s, const float4 v, float4& a){
    a.x=fmaf(s,v.x,a.x); a.y=fmaf(s,v.y,a.y); a.z=fmaf(s,v.z,a.z); a.w=fmaf(s,v.w,a.w);
}
__device__ __forceinline__ int jrow(int r, int hcb){ return ((r>>3)<<9) + hcb + (r&7); }
__device__ __forceinline__ unsigned ld32(const __nv_bfloat16* p){ return *(const unsigned*)p; }

__device__ __forceinline__ void ev_arrive(int par){
    __threadfence(); __syncthreads();
    if (threadIdx.x == 0) {
        if (atomicAdd(&g_cnt2[par],1u) == NBLK-1) { g_cnt2[par]=0; __threadfence(); atomicAdd(&g_gen,1u); }
    }
}
__device__ __forceinline__ void ev_wait(unsigned base, unsigned n){
    if (threadIdx.x == 0) { while ((int)(*(volatile unsigned*)&g_gen - base) < (int)n) {} __threadfence(); }
    __syncthreads();
}
__device__ __forceinline__ unsigned smaddr(const void* p){
    unsigned a; asm("{.reg .u64 t; cvta.to.shared.u64 t,%1; cvt.u32.u64 %0,t;}":"=r"(a):"l"(p)); return a;
}
__device__ __forceinline__ void cpa16(unsigned d, const void* s){
    asm volatile("cp.async.cg.shared.global [%0],[%1],16;"::"r"(d),"l"(s));
}
#define CP_COMMIT() asm volatile("cp.async.commit_group;")
#define CP_WAIT0()  asm volatile("cp.async.wait_group 0;" ::: "memory")

__device__ __forceinline__ void mma16816(float4& c, const uint4 a, const uint2 b){
    asm volatile("mma.sync.aligned.m16n8k16.row.col.f32.bf16.bf16.f32 "
        "{%0,%1,%2,%3},{%4,%5,%6,%7},{%8,%9},{%0,%1,%2,%3};"
        : "+f"(c.x), "+f"(c.y), "+f"(c.z), "+f"(c.w)
        : "r"(a.x), "r"(a.y), "r"(a.z), "r"(a.w), "r"(b.x), "r"(b.y));
}

// prefetch one chunk: W 32 rows + H 64 rows, hi+lo planes, 128 bf16 per row
__device__ __forceinline__ void pf_chunk(__nv_bfloat16* sb, int slot,
        const __nv_bfloat16* wh, const __nv_bfloat16* wl,
        const __nv_bfloat16* hh, const __nv_bfloat16* hl, int k0, int tid){
    __nv_bfloat16* base = sb + slot*SLOT_BF;
#pragma unroll
    for (int i = 0; i < 12; ++i) {
        int c = tid + NTHR*i;          // 0..3071
        int row = c >> 4, cc = c & 15;
        const __nv_bfloat16* s; unsigned d;
        if (row < 32)       { s = wh + row*512;       d = smaddr(base + S_WHI + row*KHP); }
        else if (row < 64)  { s = wl + (row-32)*512;  d = smaddr(base + S_WLO + (row-32)*KHP); }
        else if (row < 128) { s = hh + (row-64)*512;  d = smaddr(base + S_HHI + (row-64)*KHP); }
        else                { s = hl + (row-128)*512; d = smaddr(base + S_HLO + (row-128)*KHP); }
        cpa16(d + cc*16, s + k0 + cc*8);
    }
    CP_COMMIT();
}

// one K=128 chunk of GEMM; warp covers M=32 (2 m16) x N=32 (4 n8), k-group kg
__device__ __forceinline__ void gemm_chunk(const __nv_bfloat16* sb, int kg, int nb,
                                           int lg, int tg, float4 C[2][4]){
#pragma unroll
    for (int k2 = 0; k2 < 2; ++k2) {
        int kk = (kg*2 + k2)*16;
        uint4 Ah[2], Al[2];
#pragma unroll
        for (int i = 0; i < 2; ++i) {
            const __nv_bfloat16* p = sb + S_WHI + (16*i + lg)*KHP + kk + 2*tg;
            Ah[i].x = ld32(p);            Ah[i].y = ld32(p + 8*KHP);
            Ah[i].z = ld32(p + 8);        Ah[i].w = ld32(p + 8*KHP + 8);
            const __nv_bfloat16* q = p + (S_WLO - S_WHI);
            Al[i].x = ld32(q);            Al[i].y = ld32(q + 8*KHP);
            Al[i].z = ld32(q + 8);        Al[i].w = ld32(q + 8*KHP + 8);
        }
        uint2 Bh[4], Bl[4];
#pragma unroll
        for (int nt = 0; nt < 4; ++nt) {
            const __nv_bfloat16* p = sb + S_HHI + (nb + nt*8 + lg)*KHP + kk + 2*tg;
            Bh[nt].x = ld32(p); Bh[nt].y = ld32(p + 8);
            const __nv_bfloat16* q = p + (S_HLO - S_HHI);
            Bl[nt].x = ld32(q); Bl[nt].y = ld32(q + 8);
        }
#pragma unroll
        for (int i = 0; i < 2; ++i)
#pragma unroll
            for (int nt = 0; nt < 4; ++nt) {
                mma16816(C[i][nt], Ah[i], Bh[nt]);
                mma16816(C[i][nt], Ah[i], Bl[nt]);
                mma16816(C[i][nt], Al[i], Bh[nt]);
            }
    }
}

__device__ __forceinline__ void store_C(float* sg, float4 C[2][4], int kg, int nb, int lg, int tg){
#pragma unroll
    for (int i = 0; i < 2; ++i)
#pragma unroll
        for (int nt = 0; nt < 4; ++nt) {
            float* s = sg + kg*2048 + (16*i + lg)*64 + nb + nt*8 + 2*tg;
            *(float2*)s = make_float2(C[i][nt].x, C[i][nt].y);
            *(float2*)(s + 512) = make_float2(C[i][nt].z, C[i][nt].w);
        }
}

// gate reduction + cell math + state-plane writes (thread: b = tid&63, hc = 2q,2q+1)
__device__ __forceinline__ void cell_phase(float* smf, int tid, int hcb,
        const float* sbias, const float* swih, const float* x, int te,
        float* cstate, __nv_bfloat16* ph_hi, __nv_bfloat16* ph_lo,
        __nv_bfloat16* pc_hi, __nv_bfloat16* pc_lo, float* hist){
    float* sg = smf + F_SG;
    int b = tid & 63, q = tid >> 6;
    float xb = swih ? __ldg(x + b*Tm + te) : 0.f;
    float hv[2], cv[2];
#pragma unroll
    for (int e = 0; e < 2; ++e) {
        int hc = 2*q + e;
        float gs[4];
#pragma unroll
        for (int g = 0; g < 4; ++g) {
            int r = g*8 + hc;
            float v = sg[r*64+b] + sg[2048 + r*64+b] + sg[4096 + r*64+b] + sg[6144 + r*64+b] + sbias[r];
            if (swih) v = fmaf(swih[r], xb, v);
            gs[g] = v;
        }
        float co = cstate[hc*64 + b];
        float cn = sigf(gs[1])*co + sigf(gs[0])*tanhf(gs[2]);
        cstate[hc*64 + b] = cn;
        hv[e] = sigf(gs[3])*tanhf(cn);
        cv[e] = cn;
    }
    int off = b*512 + hcb + 2*q;
    __nv_bfloat16 a0 = __float2bfloat16(hv[0]), a1 = __float2bfloat16(hv[1]);
    *(__nv_bfloat162*)(ph_hi + off) = __halves2bfloat162(a0, a1);
    *(__nv_bfloat162*)(ph_lo + off) =
        __floats2bfloat162_rn(hv[0]-__bfloat162float(a0), hv[1]-__bfloat162float(a1));
    if (pc_hi) {
        __nv_bfloat16 c0 = __float2bfloat16(cv[0]), c1 = __float2bfloat16(cv[1]);
        *(__nv_bfloat162*)(pc_hi + off) = __halves2bfloat162(c0, c1);
        *(__nv_bfloat162*)(pc_lo + off) =
            __floats2bfloat162_rn(cv[0]-__bfloat162float(c0), cv[1]-__bfloat162float(c1));
    }
    if (hist) *(float2*)(hist + off) = make_float2(cv[0], cv[1]);
}

__global__ void noop_kernel() {}

extern "C" __global__ void __launch_bounds__(NTHR, 1)
lstm_persist(const float* __restrict__ x,
             const float* wih1, const float* whh1, const float* bih1, const float* bhh1,
             const float* wih2, const float* whh2, const float* bih2, const float* bhh2,
             const float* wih3, const float* whh3, const float* bih3, const float* bhh3,
             const float* wih4, const float* whh4, const float* bih4, const float* bhh4) {
    extern __shared__ __align__(16) float smf[];
    __nv_bfloat16* sb = (__nv_bfloat16*)smf;

    const int tid = threadIdx.x;
    const int dir = blockIdx.x & 1;
    const int gb  = blockIdx.x >> 1;
    const int hcb = gb << 3;
    const unsigned gbase = *(volatile unsigned*)&g_gen;

    const float* WIH1 = dir ? wih3 : wih1;
    const float* BIH1 = dir ? bih3 : bih1;
    const float* BHH1 = dir ? bhh3 : bhh1;
    const float* BIH2 = dir ? bih4 : bih2;
    const float* BHH2 = dir ? bhh4 : bhh2;
    const float* Wsrc[3] = { dir ? whh3 : whh1, dir ? whh4 : whh2, dir ? wih4 : wih2 };

    // init: biases, c-state zero, weight split, state-plane zero
    if (tid < 32) {
        int j = jrow(tid, hcb);
        smf[F_B1 + tid] = __ldg(BIH1 + j) + __ldg(BHH1 + j);
        smf[F_B2 + tid] = __ldg(BIH2 + j) + __ldg(BHH2 + j);
        smf[F_XW + tid] = __ldg(WIH1 + j);
    }
    for (int i = tid; i < 1024; i += NTHR) smf[F_CS + i] = 0.f;
#pragma unroll 1
    for (int p = 0; p < 3; ++p) {
        int pidx = dir*3 + p;
        for (int idx = tid; idx < 32*512; idx += NTHR) {
            int r = idx >> 9, k = idx & 511;
            float v = __ldg(Wsrc[p] + (size_t)jrow(r, hcb)*512 + k);
            __nv_bfloat16 hi = __float2bfloat16(v);
            gWh[pidx][gb][idx] = hi;
            gWl[pidx][gb][idx] = __float2bfloat16(v - __bfloat162float(hi));
        }
    }
    {
        const int gt = blockIdx.x*NTHR + tid, stride = NBLK*NTHR;
        unsigned* z[4] = { (unsigned*)gH1h, (unsigned*)gH1l, (unsigned*)gH2h, (unsigned*)gH2l };
        for (int a = 0; a < 4; ++a)
            for (int i = gt; i < 2*2*Bm*Hm/2; i += stride) z[a][i] = 0u;
    }
    ev_arrive(1);
    ev_wait(gbase, 1);

    // warp org: 8 warps = kg(0..3) x nh(0..1); lanes: lg = lane>>2, tg = lane&3
    const int lane = tid & 31, wid = tid >> 5;
    const int kg = wid >> 1, nb = (wid & 1) * 32;
    const int lg = lane >> 2, tg = lane & 3;

    const __nv_bfloat16* wH[3]; const __nv_bfloat16* wL[3];
#pragma unroll
    for (int p = 0; p < 3; ++p) { wH[p] = gWh[dir*3+p][gb]; wL[p] = gWl[dir*3+p][gb]; }

    // prime: item0 of t=0 (h1 parity 1 = zeros)
    pf_chunk(sb, 0, wH[0], wL[0], gH1h[dir][1], gH1l[dir][1], 0, tid);

    float4 C[2][4];
#pragma unroll
    for (int i = 0; i < 2; ++i)
#pragma unroll
        for (int nt = 0; nt < 4; ++nt) C[i][nt] = make_float4(0,0,0,0);

#pragma unroll 1
    for (int t = 0; t < Tm; ++t) {
        const int wb = t & 1, rb = wb ^ 1;
        const int te = dir ? (Tm - 1 - t) : t;
        const __nv_bfloat16* hH[3] = { gH1h[dir][rb], gH2h[dir][rb], gC1h[dir] };
        const __nv_bfloat16* hL[3] = { gH1l[dir][rb], gH2l[dir][rb], gC1l[dir] };

#pragma unroll 1
        for (int g = 0; g < 12; ++g) {
            CP_WAIT0(); __syncthreads();
            if (g == 3) ev_wait(gbase, 2u*t + 1u);   // evB(t-1): h2 planes ready
            if (g == 7) ev_wait(gbase, 2u*t + 2u);   // evA(t): c1 planes ready
            int n = g + 1;
            if (n < 12)
                pf_chunk(sb, n & 1, wH[n>>2], wL[n>>2], hH[n>>2], hL[n>>2], (n & 3)*KC, tid);
            else if (t + 1 < Tm)
                pf_chunk(sb, 0, wH[0], wL[0], gH1h[dir][wb], gH1l[dir][wb], 0, tid);
            gemm_chunk(sb + (g & 1)*SLOT_BF, kg, nb, lg, tg, C);

            if (g == 3) {   // epilogue A
                store_C(smf + F_SG, C, kg, nb, lg, tg);
                __syncthreads();
                cell_phase(smf, tid, hcb, smf + F_B1, smf + F_XW, x, te,
                           smf + F_CS, gH1h[dir][wb], gH1l[dir][wb],
                           gC1h[dir], gC1l[dir], (float*)0);
#pragma unroll
                for (int i = 0; i < 2; ++i)
#pragma unroll
                    for (int nt = 0; nt < 4; ++nt) C[i][nt] = make_float4(0,0,0,0);
                ev_arrive(0);                         // evA(t)
            }
            if (g == 11) {  // epilogue B
                store_C(smf + F_SG, C, kg, nb, lg, tg);
                __syncthreads();
                cell_phase(smf, tid, hcb, smf + F_B2, (const float*)0, x, te,
                           smf + F_CS + 512, gH2h[dir][wb], gH2l[dir][wb],
                           (__nv_bfloat16*)0, (__nv_bfloat16*)0, g_hist[dir][t]);
#pragma unroll
                for (int i = 0; i < 2; ++i)
#pragma unroll
                    for (int nt = 0; nt < 4; ++nt) C[i][nt] = make_float4(0,0,0,0);
                ev_arrive(1);                         // evB(t)
            }
        }
    }
    ev_wait(gbase, 2u*Tm + 1u);
}

// ---- final FC (unchanged, reads g_hist) ----
__device__ __forceinline__ void stage_T(const float* __restrict__ src,
                                        float* __restrict__ sT, int tid) {
#pragma unroll
    for (int it = 0; it < 32; ++it) {
        int id = tid + 256*it;
        int lane = id & 31, grp = id >> 5;
        int kl = lane & 7, bg = lane >> 3;
        int kq = ((grp & 15) << 3) | kl;
        int b  = ((grp >> 4) << 2) | bg;
        float4 v = __ldcg((const float4*)(src + b*Hm + (kq << 2)));
        float* p = sT + kq*SQ + b;
        p[0] = v.x; p[64] = v.y; p[128] = v.z; p[192] = v.w;
    }
}

extern "C" __global__ void __launch_bounds__(256)
fc_kernel(const float* __restrict__ fcw, const float* __restrict__ fcb,
          const float* __restrict__ bfcw, const float* __restrict__ bfcb,
          float* __restrict__ out) {
    extern __shared__ __align__(16) float smq[];
    float* sT = smq;
    const int tid = threadIdx.x;
    const int d = blockIdx.x >> 9;
    const int t = blockIdx.x & 511;
    const float* W = d ? bfcw : fcw;
    const float* bias = d ? bfcb : fcb;

    stage_T(W, sT, tid);
    __syncthreads();

    const float* hb = g_hist[d][t];
    const size_t obase = (size_t)d*Bm*Tm*Cm + (size_t)t*Cm;
#pragma unroll
    for (int tt = 0; tt < 4; ++tt) {
        int tile = tid + 256*tt;
        int b = tile >> 4;
        int c0 = (tile & 15) << 2;
        float4 acc = *(const float4*)(bias + c0);
        const float4* hq = (const float4*)(hb + b*Hm);
        const float* wq0 = sT + c0;
#pragma unroll 4
        for (int kq = 0; kq < 128; ++kq) {
            float4 h4 = __ldg(hq + kq);
            const float* wq = wq0 + kq*SQ;
            fma4(h4.x, *(const float4*)(wq), acc);
            fma4(h4.y, *(const float4*)(wq + 64), acc);
            fma4(h4.z, *(const float4*)(wq + 128), acc);
            fma4(h4.w, *(const float4*)(wq + 192), acc);
        }
        *(float4*)(out + obase + (size_t)b*Tm*Cm + c0) = acc;
    }
}

extern "C" void kernel_launch(void* const* d_in, const int* in_sizes, int n_in,
                              void* d_out, int out_size) {
    const float* x    = (const float*)d_in[0];
    const float* wih1 = (const float*)d_in[1];
    const float* whh1 = (const float*)d_in[2];
    const float* bih1 = (const float*)d_in[3];
    const float* bhh1 = (const float*)d_in[4];
    const float* wih2 = (const float*)d_in[5];
    const float* whh2 = (const float*)d_in[6];
    const float* bih2 = (const float*)d_in[7];
    const float* bhh2 = (const float*)d_in[8];
    const float* wih3 = (const float*)d_in[9];
    const float* whh3 = (const float*)d_in[10];
    const float* bih3 = (const float*)d_in[11];
    const float* bhh3 = (const float*)d_in[12];
    const float* wih4 = (const float*)d_in[13];
    const float* whh4 = (const float*)d_in[14];
    const float* bih4 = (const float*)d_in[15];
    const float* bhh4 = (const float*)d_in[16];
    const float* fcw  = (const float*)d_in[17];
    const float* fcb  = (const float*)d_in[18];
    const float* bfcw = (const float*)d_in[19];
    const float* bfcb = (const float*)d_in[20];

    static int attr_done = 0;
    if (!attr_done) {
        cudaFuncSetAttribute(lstm_persist, cudaFuncAttributeMaxDynamicSharedMemorySize, SM_BYTES);
        cudaFuncSetAttribute(fc_kernel, cudaFuncAttributeMaxDynamicSharedMemorySize, FC_SMB);
        attr_done = 1;
    }

    for (int i = 0; i < 3; ++i) noop_kernel<<<1, 32>>>();

    lstm_persist<<<NBLK, NTHR, SM_BYTES>>>(x,
        wih1, whh1, bih1, bhh1, wih2, whh2, bih2, bhh2,
        wih3, whh3, bih3, bhh3, wih4, whh4, bih4, bhh4);

    fc_kernel<<<2*Tm, 256, FC_SMB>>>(fcw, fcb, bfcw, bfcb, (float*)d_out);
}

// round 15
// speedup vs baseline: 1.2327x; 1.0146x over previous
#include <cuda_runtime.h>
#include <cuda_bf16.h>
#include <math.h>
#include <stdint.h>

#define Bm 64
#define Tm 512
#define Hm 512
#define Cm 64
#define NBLK 128
#define NTHR 256
#define KC 128                 // K chunk
#define KHP 136                // padded smem row stride (bf16), ==8 mod 64
#define S_WHI 0
#define S_WLO (32*KHP)
#define S_HHI (64*KHP)
#define S_HLO (128*KHP)
#define SLOT_BF (192*KHP)      // 26112 bf16 per slot
#define NSLOT 3
// float offsets after 3 slots (3*26112 bf16 = 39168 floats)
#define F_SG   39168
#define F_CS   (F_SG + 4*2048)
#define F_B1   (F_CS + 1024)
#define F_B2   (F_B1 + 32)
#define F_XW   (F_B2 + 32)
#define SM_FLOATS (F_XW + 32)
#define SM_BYTES (SM_FLOATS*4)
#define SQ 260
#define FC_SMB (128*SQ*4)

__device__ __nv_bfloat16 gWh[6][64][32*512];
__device__ __nv_bfloat16 gWl[6][64][32*512];
__device__ __nv_bfloat16 gH1h[2][2][Bm*Hm], gH1l[2][2][Bm*Hm];
__device__ __nv_bfloat16 gH2h[2][2][Bm*Hm], gH2l[2][2][Bm*Hm];
__device__ __nv_bfloat16 gC1h[2][Bm*Hm],    gC1l[2][Bm*Hm];
__device__ float g_hist[2][Tm][Bm*Hm];
__device__ unsigned g_cnt2[2] = {0, 0};
__device__ unsigned g_gen = 0;

__device__ __forceinline__ float sigf(float v){ return 1.f/(1.f+expf(-v)); }
__device__ __forceinline__ void fma4(float s, const float4 v, float4& a){
    a.x=fmaf(s,v.x,a.x); a.y=fmaf(s,v.y,a.y); a.z=fmaf(s,v.z,a.z); a.w=fmaf(s,v.w,a.w);
}
__device__ __forceinline__ int jrow(int r, int hcb){ return ((r>>3)<<9) + hcb + (r&7); }

__device__ __forceinline__ void ev_arrive(int par){
    __threadfence(); __syncthreads();
    if (threadIdx.x == 0) {
        if (atomicAdd(&g_cnt2[par],1u) == NBLK-1) { g_cnt2[par]=0; __threadfence(); atomicAdd(&g_gen,1u); }
    }
}
__device__ __forceinline__ void ev_wait(unsigned base, unsigned n){
    if (threadIdx.x == 0) { while ((int)(*(volatile unsigned*)&g_gen - base) < (int)n) {} __threadfence(); }
    __syncthreads();
}
__device__ __forceinline__ unsigned smaddr(const void* p){
    unsigned a; asm("{.reg .u64 t; cvta.to.shared.u64 t,%1; cvt.u32.u64 %0,t;}":"=r"(a):"l"(p)); return a;
}
__device__ __forceinline__ void cpa16(unsigned d, const void* s){
    asm volatile("cp.async.cg.shared.global [%0],[%1],16;"::"r"(d),"l"(s));
}
#define CP_COMMIT() asm volatile("cp.async.commit_group;")
#define CP_WAIT1()  asm volatile("cp.async.wait_group 1;" ::: "memory")

__device__ __forceinline__ void ldsm4(uint4& d, unsigned a){
    asm volatile("ldmatrix.sync.aligned.m8n8.x4.shared.b16 {%0,%1,%2,%3},[%4];"
        : "=r"(d.x), "=r"(d.y), "=r"(d.z), "=r"(d.w) : "r"(a));
}
__device__ __forceinline__ void mma16816(float4& c, const uint4 a, const uint2 b){
    asm volatile("mma.sync.aligned.m16n8k16.row.col.f32.bf16.bf16.f32 "
        "{%0,%1,%2,%3},{%4,%5,%6,%7},{%8,%9},{%0,%1,%2,%3};"
        : "+f"(c.x), "+f"(c.y), "+f"(c.z), "+f"(c.w)
        : "r"(a.x), "r"(a.y), "r"(a.z), "r"(a.w), "r"(b.x), "r"(b.y));
}

__device__ __forceinline__ void pf_chunk(__nv_bfloat16* sb, int slot,
        const __nv_bfloat16* wh, const __nv_bfloat16* wl,
        const __nv_bfloat16* hh, const __nv_bfloat16* hl, int k0, int tid){
    __nv_bfloat16* base = sb + slot*SLOT_BF;
#pragma unroll
    for (int i = 0; i < 12; ++i) {
        int c = tid + NTHR*i;
        int row = c >> 4, cc = c & 15;
        const __nv_bfloat16* s; unsigned d;
        if (row < 32)       { s = wh + row*512;       d = smaddr(base + S_WHI + row*KHP); }
        else if (row < 64)  { s = wl + (row-32)*512;  d = smaddr(base + S_WLO + (row-32)*KHP); }
        else if (row < 128) { s = hh + (row-64)*512;  d = smaddr(base + S_HHI + (row-64)*KHP); }
        else                { s = hl + (row-128)*512; d = smaddr(base + S_HLO + (row-128)*KHP); }
        cpa16(d + cc*16, s + k0 + cc*8);
    }
    CP_COMMIT();
}

// one K=128 chunk; warp = M32 x N32 tile at n-offset nb, k-group kg. ldmatrix loads.
__device__ __forceinline__ void gemm_chunk(const __nv_bfloat16* sb, int kg, int nb,
                                           int lane, float4 C[2][4]){
    const int aRow = lane & 15, aK = (lane >> 4) * 8;
    const int bRow = ((lane >> 4) << 3) + (lane & 7), bK = ((lane >> 3) & 1) * 8;
#pragma unroll
    for (int k2 = 0; k2 < 2; ++k2) {
        int kk = (kg*2 + k2)*16;
        uint4 Ah[2], Al[2], Bh2[2], Bl2[2];
#pragma unroll
        for (int i = 0; i < 2; ++i) {
            unsigned pa = smaddr(sb + S_WHI + (16*i + aRow)*KHP + kk + aK);
            ldsm4(Ah[i], pa);
            ldsm4(Al[i], pa + (S_WLO - S_WHI)*2);
        }
#pragma unroll
        for (int h = 0; h < 2; ++h) {
            unsigned pb = smaddr(sb + S_HHI + (nb + h*16 + bRow)*KHP + kk + bK);
            ldsm4(Bh2[h], pb);
            ldsm4(Bl2[h], pb + (S_HLO - S_HHI)*2);
        }
#pragma unroll
        for (int i = 0; i < 2; ++i)
#pragma unroll
            for (int h = 0; h < 2; ++h) {
                uint2 bh0 = make_uint2(Bh2[h].x, Bh2[h].y);
                uint2 bh1 = make_uint2(Bh2[h].z, Bh2[h].w);
                uint2 bl0 = make_uint2(Bl2[h].x, Bl2[h].y);
                uint2 bl1 = make_uint2(Bl2[h].z, Bl2[h].w);
                mma16816(C[i][2*h],   Ah[i], bh0);
                mma16816(C[i][2*h],   Ah[i], bl0);
                mma16816(C[i][2*h],   Al[i], bh0);
                mma16816(C[i][2*h+1], Ah[i], bh1);
                mma16816(C[i][2*h+1], Ah[i], bl1);
                mma16816(C[i][2*h+1], Al[i], bh1);
            }
    }
}

__device__ __forceinline__ void store_C(float* sg, float4 C[2][4], int kg, int nb, int lg, int tg){
#pragma unroll
    for (int i = 0; i < 2; ++i)
#pragma unroll
        for (int nt = 0; nt < 4; ++nt) {
            float* s = sg + kg*2048 + (16*i + lg)*64 + nb + nt*8 + 2*tg;
            *(float2*)s = make_float2(C[i][nt].x, C[i][nt].y);
            *(float2*)(s + 512) = make_float2(C[i][nt].z, C[i][nt].w);
        }
}

__device__ __forceinline__ void cell_phase(float* smf, int tid, int hcb,
        const float* sbias, const float* swih, const float* x, int te,
        float* cstate, __nv_bfloat16* ph_hi, __nv_bfloat16* ph_lo,
        __nv_bfloat16* pc_hi, __nv_bfloat16* pc_lo, float* hist){
    float* sg = smf + F_SG;
    int b = tid & 63, q = tid >> 6;
    float xb = swih ? __ldg(x + b*Tm + te) : 0.f;
    float hv[2], cv[2];
#pragma unroll
    for (int e = 0; e < 2; ++e) {
        int hc = 2*q + e;
        float gs[4];
#pragma unroll
        for (int g = 0; g < 4; ++g) {
            int r = g*8 + hc;
            float v = sg[r*64+b] + sg[2048 + r*64+b] + sg[4096 + r*64+b] + sg[6144 + r*64+b] + sbias[r];
            if (swih) v = fmaf(swih[r], xb, v);
            gs[g] = v;
        }
        float co = cstate[hc*64 + b];
        float cn = sigf(gs[1])*co + sigf(gs[0])*tanhf(gs[2]);
        cstate[hc*64 + b] = cn;
        hv[e] = sigf(gs[3])*tanhf(cn);
        cv[e] = cn;
    }
    int off = b*512 + hcb + 2*q;
    __nv_bfloat16 a0 = __float2bfloat16(hv[0]), a1 = __float2bfloat16(hv[1]);
    *(__nv_bfloat162*)(ph_hi + off) = __halves2bfloat162(a0, a1);
    *(__nv_bfloat162*)(ph_lo + off) =
        __floats2bfloat162_rn(hv[0]-__bfloat162float(a0), hv[1]-__bfloat162float(a1));
    if (pc_hi) {
        __nv_bfloat16 c0 = __float2bfloat16(cv[0]), c1 = __float2bfloat16(cv[1]);
        *(__nv_bfloat162*)(pc_hi + off) = __halves2bfloat162(c0, c1);
        *(__nv_bfloat162*)(pc_lo + off) =
            __floats2bfloat162_rn(cv[0]-__bfloat162float(c0), cv[1]-__bfloat162float(c1));
    }
    if (hist) *(float2*)(hist + off) = make_float2(cv[0], cv[1]);
}

__global__ void noop_kernel() {}

extern "C" __global__ void __launch_bounds__(NTHR, 1)
lstm_persist(const float* __restrict__ x,
             const float* wih1, const float* whh1, const float* bih1, const float* bhh1,
             const float* wih2, const float* whh2, const float* bih2, const float* bhh2,
             const float* wih3, const float* whh3, const float* bih3, const float* bhh3,
             const float* wih4, const float* whh4, const float* bih4, const float* bhh4) {
    extern __shared__ __align__(16) float smf[];
    __nv_bfloat16* sb = (__nv_bfloat16*)smf;

    const int tid = threadIdx.x;
    const int dir = blockIdx.x & 1;
    const int gb  = blockIdx.x >> 1;
    const int hcb = gb << 3;
    const unsigned gbase = *(volatile unsigned*)&g_gen;

    const float* WIH1 = dir ? wih3 : wih1;
    const float* BIH1 = dir ? bih3 : bih1;
    const float* BHH1 = dir ? bhh3 : bhh1;
    const float* BIH2 = dir ? bih4 : bih2;
    const float* BHH2 = dir ? bhh4 : bhh2;
    const float* Wsrc[3] = { dir ? whh3 : whh1, dir ? whh4 : whh2, dir ? wih4 : wih2 };

    if (tid < 32) {
        int j = jrow(tid, hcb);
        smf[F_B1 + tid] = __ldg(BIH1 + j) + __ldg(BHH1 + j);
        smf[F_B2 + tid] = __ldg(BIH2 + j) + __ldg(BHH2 + j);
        smf[F_XW + tid] = __ldg(WIH1 + j);
    }
    for (int i = tid; i < 1024; i += NTHR) smf[F_CS + i] = 0.f;
#pragma unroll 1
    for (int p = 0; p < 3; ++p) {
        int pidx = dir*3 + p;
        for (int idx = tid; idx < 32*512; idx += NTHR) {
            int r = idx >> 9, k = idx & 511;
            float v = __ldg(Wsrc[p] + (size_t)jrow(r, hcb)*512 + k);
            __nv_bfloat16 hi = __float2bfloat16(v);
            gWh[pidx][gb][idx] = hi;
            gWl[pidx][gb][idx] = __float2bfloat16(v - __bfloat162float(hi));
        }
    }
    {
        const int gt = blockIdx.x*NTHR + tid, stride = NBLK*NTHR;
        unsigned* z[4] = { (unsigned*)gH1h, (unsigned*)gH1l, (unsigned*)gH2h, (unsigned*)gH2l };
        for (int a = 0; a < 4; ++a)
            for (int i = gt; i < 2*2*Bm*Hm/2; i += stride) z[a][i] = 0u;
    }
    ev_arrive(1);
    ev_wait(gbase, 1);

    const int lane = tid & 31, wid = tid >> 5;
    const int kg = wid >> 1, nb = (wid & 1) * 32;
    const int lg = lane >> 2, tg = lane & 3;

    const __nv_bfloat16* wH[3]; const __nv_bfloat16* wL[3];
#pragma unroll
    for (int p = 0; p < 3; ++p) { wH[p] = gWh[dir*3+p][gb]; wL[p] = gWl[dir*3+p][gb]; }

    // prime: chunks 0 and 1 of step 0 pass 1 (h1 parity 1 = zeros)
    pf_chunk(sb, 0, wH[0], wL[0], gH1h[dir][1], gH1l[dir][1], 0, tid);
    pf_chunk(sb, 1, wH[0], wL[0], gH1h[dir][1], gH1l[dir][1], KC, tid);

    float4 C[2][4];
#pragma unroll
    for (int i = 0; i < 2; ++i)
#pragma unroll
        for (int nt = 0; nt < 4; ++nt) C[i][nt] = make_float4(0,0,0,0);

#pragma unroll 1
    for (int t = 0; t < Tm; ++t) {
        const int wb = t & 1, rb = wb ^ 1;
        const int te = dir ? (Tm - 1 - t) : t;
        const __nv_bfloat16* hH[3] = { gH1h[dir][rb], gH2h[dir][rb], gC1h[dir] };
        const __nv_bfloat16* hL[3] = { gH1l[dir][rb], gH2l[dir][rb], gC1l[dir] };

#pragma unroll 1
        for (int g = 0; g < 12; ++g) {
            CP_WAIT1(); __syncthreads();
            if (g == 2) ev_wait(gbase, 2u*t + 1u);   // evB(t-1): h2 planes ready
            if (g == 6) ev_wait(gbase, 2u*t + 2u);   // evA(t): c1 planes ready
            int n = g + 2;
            if (n < 12)
                pf_chunk(sb, n % NSLOT, wH[n>>2], wL[n>>2], hH[n>>2], hL[n>>2], (n & 3)*KC, tid);
            else if (t + 1 < Tm)
                pf_chunk(sb, n % NSLOT, wH[0], wL[0], gH1h[dir][wb], gH1l[dir][wb], (n-12)*KC, tid);
            gemm_chunk(sb + (g % NSLOT)*SLOT_BF, kg, nb, lane, C);

            if (g == 3) {
                store_C(smf + F_SG, C, kg, nb, lg, tg);
                __syncthreads();
                cell_phase(smf, tid, hcb, smf + F_B1, smf + F_XW, x, te,
                           smf + F_CS, gH1h[dir][wb], gH1l[dir][wb],
                           gC1h[dir], gC1l[dir], (float*)0);
#pragma unroll
                for (int i = 0; i < 2; ++i)
#pragma unroll
                    for (int nt = 0; nt < 4; ++nt) C[i][nt] = make_float4(0,0,0,0);
                ev_arrive(0);
            }
            if (g == 11) {
                store_C(smf + F_SG, C, kg, nb, lg, tg);
                __syncthreads();
                cell_phase(smf, tid, hcb, smf + F_B2, (const float*)0, x, te,
                           smf + F_CS + 512, gH2h[dir][wb], gH2l[dir][wb],
                           (__nv_bfloat16*)0, (__nv_bfloat16*)0, g_hist[dir][t]);
#pragma unroll
                for (int i = 0; i < 2; ++i)
#pragma unroll
                    for (int nt = 0; nt < 4; ++nt) C[i][nt] = make_float4(0,0,0,0);
                ev_arrive(1);
            }
        }
    }
    ev_wait(gbase, 2u*Tm + 1u);
}

// ---- final FC (unchanged) ----
__device__ __forceinline__ void stage_T(const float* __restrict__ src,
                                        float* __restrict__ sT, int tid) {
#pragma unroll
    for (int it = 0; it < 32; ++it) {
        int id = tid + 256*it;
        int lane = id & 31, grp = id >> 5;
        int kl = lane & 7, bg = lane >> 3;
        int kq = ((grp & 15) << 3) | kl;
        int b  = ((grp >> 4) << 2) | bg;
        float4 v = __ldcg((const float4*)(src + b*Hm + (kq << 2)));
        float* p = sT + kq*SQ + b;
        p[0] = v.x; p[64] = v.y; p[128] = v.z; p[192] = v.w;
    }
}

extern "C" __global__ void __launch_bounds__(256)
fc_kernel(const float* __restrict__ fcw, const float* __restrict__ fcb,
          const float* __restrict__ bfcw, const float* __restrict__ bfcb,
          float* __restrict__ out) {
    extern __shared__ __align__(16) float smq[];
    float* sT = smq;
    const int tid = threadIdx.x;
    const int d = blockIdx.x >> 9;
    const int t = blockIdx.x & 511;
    const float* W = d ? bfcw : fcw;
    const float* bias = d ? bfcb : fcb;

    stage_T(W, sT, tid);
    __syncthreads();

    const float* hb = g_hist[d][t];
    const size_t obase = (size_t)d*Bm*Tm*Cm + (size_t)t*Cm;
#pragma unroll
    for (int tt = 0; tt < 4; ++tt) {
        int tile = tid + 256*tt;
        int b = tile >> 4;
        int c0 = (tile & 15) << 2;
        float4 acc = *(const float4*)(bias + c0);
        const float4* hq = (const float4*)(hb + b*Hm);
        const float* wq0 = sT + c0;
#pragma unroll 4
        for (int kq = 0; kq < 128; ++kq) {
            float4 h4 = __ldg(hq + kq);
            const float* wq = wq0 + kq*SQ;
            fma4(h4.x, *(const float4*)(wq), acc);
            fma4(h4.y, *(const float4*)(wq + 64), acc);
            fma4(h4.z, *(const float4*)(wq + 128), acc);
            fma4(h4.w, *(const float4*)(wq + 192), acc);
        }
        *(float4*)(out + obase + (size_t)b*Tm*Cm + c0) = acc;
    }
}

extern "C" void kernel_launch(void* const* d_in, const int* in_sizes, int n_in,
                              void* d_out, int out_size) {
    const float* x    = (const float*)d_in[0];
    const float* wih1 = (const float*)d_in[1];
    const float* whh1 = (const float*)d_in[2];
    const float* bih1 = (const float*)d_in[3];
    const float* bhh1 = (const float*)d_in[4];
    const float* wih2 = (const float*)d_in[5];
    const float* whh2 = (const float*)d_in[6];
    const float* bih2 = (const float*)d_in[7];
    const float* bhh2 = (const float*)d_in[8];
    const float* wih3 = (const float*)d_in[9];
    const float* whh3 = (const float*)d_in[10];
    const float* bih3 = (const float*)d_in[11];
    const float* bhh3 = (const float*)d_in[12];
    const float* wih4 = (const float*)d_in[13];
    const float* whh4 = (const float*)d_in[14];
    const float* bih4 = (const float*)d_in[15];
    const float* bhh4 = (const float*)d_in[16];
    const float* fcw  = (const float*)d_in[17];
    const float* fcb  = (const float*)d_in[18];
    const float* bfcw = (const float*)d_in[19];
    const float* bfcb = (const float*)d_in[20];

    static int attr_done = 0;
    if (!attr_done) {
        cudaFuncSetAttribute(lstm_persist, cudaFuncAttributeMaxDynamicSharedMemorySize, SM_BYTES);
        cudaFuncSetAttribute(fc_kernel, cudaFuncAttributeMaxDynamicSharedMemorySize, FC_SMB);
        attr_done = 1;
    }

    for (int i = 0; i < 3; ++i) noop_kernel<<<1, 32>>>();

    lstm_persist<<<NBLK, NTHR, SM_BYTES>>>(x,
        wih1, whh1, bih1, bhh1, wih2, whh2, bih2, bhh2,
        wih3, whh3, bih3, bhh3, wih4, whh4, bih4, bhh4);

    fc_kernel<<<2*Tm, 256, FC_SMB>>>(fcw, fcb, bfcw, bfcb, (float*)d_out);
}